// round 10
// baseline (speedup 1.0000x reference)
#include <cuda_runtime.h>
#include <cuda_fp16.h>
#include <math.h>
#include <stdint.h>

#define Q_ROWS 8192
#define K_COLS 1024
#define DDIM   1024
#define EPSV   1e-6f
#define NPART  32                 // 8 col-CTAs * 4 warp-cols

// -------- scratch (device globals; no allocation allowed) --------
__device__ float g_a[Q_ROWS];
__device__ float g_b[K_COLS];
__device__ float g_Sp[NPART][Q_ROWS];
__device__ float g_Tp[NPART][Q_ROWS];
__device__ float g_Mp[NPART][Q_ROWS];
__device__ __half g_qh[(size_t)Q_ROWS * DDIM];   // fp16 Q (16 MB)
__device__ __half g_ph[(size_t)K_COLS * DDIM];   // fp16 P (2 MB)

static __device__ __forceinline__ uint32_t smem_u32(const void* p) {
    uint32_t a;
    asm("{ .reg .u64 t; cvta.to.shared.u64 t, %1; cvt.u32.u64 %0, t; }" : "=r"(a) : "l"(p));
    return a;
}
static __device__ __forceinline__ void cp16(uint32_t sdst, const void* gsrc) {
    asm volatile("cp.async.cg.shared.global [%0], [%1], 16;" :: "r"(sdst), "l"(gsrc));
}
#define CP_COMMIT() asm volatile("cp.async.commit_group;" ::: "memory")
#define CP_WAIT1()  asm volatile("cp.async.wait_group 1;" ::: "memory")
#define CP_WAIT0()  asm volatile("cp.async.wait_group 0;" ::: "memory")

static __device__ __forceinline__ void ldsm4(uint32_t& r0, uint32_t& r1, uint32_t& r2,
                                             uint32_t& r3, uint32_t addr) {
    asm volatile("ldmatrix.sync.aligned.m8n8.x4.shared.b16 {%0,%1,%2,%3}, [%4];"
                 : "=r"(r0), "=r"(r1), "=r"(r2), "=r"(r3) : "r"(addr));
}
static __device__ __forceinline__ void mma_f16(float& c0, float& c1, float& c2, float& c3,
                                               uint32_t a0, uint32_t a1, uint32_t a2, uint32_t a3,
                                               uint32_t b0, uint32_t b1) {
    asm volatile(
        "mma.sync.aligned.m16n8k16.row.col.f32.f16.f16.f32 "
        "{%0,%1,%2,%3}, {%4,%5,%6,%7}, {%8,%9}, {%0,%1,%2,%3};"
        : "+f"(c0), "+f"(c1), "+f"(c2), "+f"(c3)
        : "r"(a0), "r"(a1), "r"(a2), "r"(a3), "r"(b0), "r"(b1));
}

// ---------------------------------------------------------------------------
// Prep: one warp per row. Computes a/b vectors, writes fp16 copies.
// ---------------------------------------------------------------------------
__global__ void prep_kernel(const float* __restrict__ q, const float* __restrict__ p) {
    int warp = (blockIdx.x * blockDim.x + threadIdx.x) >> 5;
    int lane = threadIdx.x & 31;
    if (warp >= Q_ROWS + K_COLS) return;

    const bool isQ = warp < Q_ROWS;
    const int  r   = isQ ? warp : warp - Q_ROWS;
    const float4* row4 = (const float4*)((isQ ? q : p) + (size_t)r * DDIM);
    uint4* out4 = (uint4*)((isQ ? g_qh : g_ph) + (size_t)r * DDIM);

    float sq = 0.f, sm = 0.f;
    #pragma unroll
    for (int i = 0; i < (DDIM / 8) / 32; ++i) {
        float4 v0 = row4[2 * (lane + i * 32)];
        float4 v1 = row4[2 * (lane + i * 32) + 1];
        sq += v0.x * v0.x + v0.y * v0.y + v0.z * v0.z + v0.w * v0.w;
        sq += v1.x * v1.x + v1.y * v1.y + v1.z * v1.z + v1.w * v1.w;
        sm += v0.x + v0.y + v0.z + v0.w + v1.x + v1.y + v1.z + v1.w;
        __half2 h0 = __floats2half2_rn(v0.x, v0.y);
        __half2 h1 = __floats2half2_rn(v0.z, v0.w);
        __half2 h2 = __floats2half2_rn(v1.x, v1.y);
        __half2 h3 = __floats2half2_rn(v1.z, v1.w);
        uint4 u;
        u.x = *(uint32_t*)&h0; u.y = *(uint32_t*)&h1;
        u.z = *(uint32_t*)&h2; u.w = *(uint32_t*)&h3;
        out4[lane + i * 32] = u;
    }
    #pragma unroll
    for (int o = 16; o > 0; o >>= 1) {
        sq += __shfl_down_sync(0xFFFFFFFFu, sq, o);
        sm += __shfl_down_sync(0xFFFFFFFFu, sm, o);
    }
    if (lane == 0) {
        if (isQ) g_a[r] = sq + 2.f * EPSV * sm;
        else     g_b[r] = sq - 2.f * EPSV * sm + (float)DDIM * EPSV * EPSV;
    }
}

// ---------------------------------------------------------------------------
// fp16 mma.sync m16n8k16 GEMM + fused epilogue, BK=64, 3-stage cp.async.
// CTA 128x128, 8 warps (2x4), warp tile 64x32, 16 mainloop iterations.
// SMEM rows padded to 72 halves. 2 CTAs/SM.
// ---------------------------------------------------------------------------
#define BKH 64
#define LDH 72
#define ROW_BYTES (LDH * 2)                  // 144
#define A_BYTES   (128 * ROW_BYTES)          // 18432
#define STAGE_BYTES (2 * A_BYTES)            // 36864
#define NSTAGE 3
#define SMEM_BYTES (NSTAGE * STAGE_BYTES)    // 110592

__global__ void __launch_bounds__(256, 2) gemm_mma(float* __restrict__ post) {
    extern __shared__ char smc[];
    const uint32_t sb = smem_u32(smc);

    const int tid  = threadIdx.x;
    const int wid  = tid >> 5;
    const int lane = tid & 31;
    const int wm   = wid & 1;
    const int wn   = wid >> 1;
    const int g    = lane >> 2;
    const int cq   = lane & 3;
    const int bx = blockIdx.x, by = blockIdx.y;

    const __half* Qg = g_qh + (size_t)(by * 128) * DDIM;
    const __half* Pg = g_ph + (size_t)(bx * 128) * DDIM;

    auto issue = [&](int c, int s) {
        const int k0 = c * BKH;
        #pragma unroll
        for (int i = 0; i < 4; ++i) {
            int idx = tid + i * 256, row = idx >> 3, ch = idx & 7;
            uint32_t so = sb + s * STAGE_BYTES + row * ROW_BYTES + ch * 16;
            cp16(so, Qg + (size_t)row * DDIM + k0 + ch * 8);
            cp16(so + A_BYTES, Pg + (size_t)row * DDIM + k0 + ch * 8);
        }
        CP_COMMIT();
    };

    const uint32_t aOff = ((wm * 64 + (lane & 15)) * LDH + (lane >> 4) * 8) * 2;
    const uint32_t bOff = (uint32_t)A_BYTES +
        ((wn * 32 + (lane >> 4) * 8 + (lane & 7)) * LDH + ((lane >> 3) & 1) * 8) * 2;

    float C[4][4][4];
    #pragma unroll
    for (int i = 0; i < 4; ++i)
        #pragma unroll
        for (int j = 0; j < 4; ++j)
            #pragma unroll
            for (int r = 0; r < 4; ++r) C[i][j][r] = 0.f;

    issue(0, 0);
    issue(1, 1);

    for (int c = 0; c < 16; ++c) {
        const int s = c % NSTAGE;
        if (c < 15) CP_WAIT1(); else CP_WAIT0();
        __syncthreads();
        if (c + 2 < 16) issue(c + 2, (c + 2) % NSTAGE);

        const uint32_t aBase = sb + s * STAGE_BYTES + aOff;
        const uint32_t bBase = sb + s * STAGE_BYTES + bOff;
        #pragma unroll
        for (int ks = 0; ks < 4; ++ks) {
            const uint32_t kadd = ks * 32;
            uint32_t a[4][4], b[4][2];
            #pragma unroll
            for (int i = 0; i < 4; ++i)
                ldsm4(a[i][0], a[i][1], a[i][2], a[i][3],
                      aBase + i * (16 * ROW_BYTES) + kadd);
            #pragma unroll
            for (int jp = 0; jp < 2; ++jp)
                ldsm4(b[2 * jp][0], b[2 * jp][1], b[2 * jp + 1][0], b[2 * jp + 1][1],
                      bBase + jp * (16 * ROW_BYTES) + kadd);
            #pragma unroll
            for (int i = 0; i < 4; ++i)
                #pragma unroll
                for (int j = 0; j < 4; ++j)
                    mma_f16(C[i][j][0], C[i][j][1], C[i][j][2], C[i][j][3],
                            a[i][0], a[i][1], a[i][2], a[i][3], b[j][0], b[j][1]);
        }
    }

    // ---------------- fused epilogue on C registers ----------------
    // hoist the 8 row a-values and 8 col b-values into registers once
    float av[4][2];
    float2 bv[4];
    #pragma unroll
    for (int i = 0; i < 4; ++i) {
        av[i][0] = g_a[by * 128 + wm * 64 + i * 16 + g];
        av[i][1] = g_a[by * 128 + wm * 64 + i * 16 + 8 + g];
    }
    #pragma unroll
    for (int j = 0; j < 4; ++j)
        bv[j] = *(const float2*)&g_b[bx * 128 + wn * 32 + j * 8 + 2 * cq];

    #pragma unroll
    for (int i = 0; i < 4; ++i) {
        #pragma unroll
        for (int half = 0; half < 2; ++half) {
            const int row = by * 128 + wm * 64 + i * 16 + half * 8 + g;
            const float a0 = av[i][half];
            float S = 0.f, T = 0.f, M = 0.f;
            #pragma unroll
            for (int j = 0; j < 4; ++j) {
                const int col = bx * 128 + wn * 32 + j * 8 + 2 * cq;
                float cr0 = C[i][j][half * 2];
                float cr1 = C[i][j][half * 2 + 1];
                float d20 = a0 + bv[j].x - 2.f * cr0;
                float d21 = a0 + bv[j].y - 2.f * cr1;
                float di0 = sqrtf(fmaxf(d20, 0.f));
                float di1 = sqrtf(fmaxf(d21, 0.f));
                float e0 = __expf(-di0), e1 = __expf(-di1);
                S += e0 + e1;
                T += e0 * di0 + e1 * di1;
                M = fmaxf(M, fmaxf(e0, e1));
                *(float2*)(post + (size_t)row * K_COLS + col) = make_float2(e0, e1);
            }
            #pragma unroll
            for (int o = 1; o < 4; o <<= 1) {
                S += __shfl_xor_sync(0xFFFFFFFFu, S, o);
                T += __shfl_xor_sync(0xFFFFFFFFu, T, o);
                M = fmaxf(M, __shfl_xor_sync(0xFFFFFFFFu, M, o));
            }
            if (cq == 0) {
                const int part = bx * 4 + wn;
                g_Sp[part][row] = S;
                g_Tp[part][row] = T;
                g_Mp[part][row] = M;
            }
        }
    }
}

// ---------------------------------------------------------------------------
// Finalize: 8 rows per block (1024 blocks). Each thread issues 8 independent
// LDG.128 up front (MLP=8); warp w reduces row w's 32 partials concurrently.
// ---------------------------------------------------------------------------
__global__ void __launch_bounds__(256) finalize_kernel(float* __restrict__ post,
                                                       float* __restrict__ c_out,
                                                       float* __restrict__ h_out) {
    const int tid  = threadIdx.x;
    const int wid  = tid >> 5;
    const int lane = tid & 31;
    const int row0 = blockIdx.x * 8;
    __shared__ float sInv[8];

    // issue all 8 row-chunks early (independent loads, MLP=8)
    float4* p4 = (float4*)(post + (size_t)row0 * K_COLS);
    float4 v[8];
    #pragma unroll
    for (int k = 0; k < 8; ++k) v[k] = p4[k * 256 + tid];

    // warp w reduces row row0+w
    {
        const int row = row0 + wid;
        float S = g_Sp[lane][row];
        float T = g_Tp[lane][row];
        float M = g_Mp[lane][row];
        #pragma unroll
        for (int of = 16; of > 0; of >>= 1) {
            S += __shfl_xor_sync(0xFFFFFFFFu, S, of);
            T += __shfl_xor_sync(0xFFFFFFFFu, T, of);
            M = fmaxf(M, __shfl_xor_sync(0xFFFFFFFFu, M, of));
        }
        if (lane == 0) {
            c_out[row] = M / S;
            h_out[row] = logf(S) + T / S;
            sInv[wid] = 1.f / S;
        }
    }
    __syncthreads();

    #pragma unroll
    for (int k = 0; k < 8; ++k) {
        const float inv = sInv[k];
        v[k].x *= inv; v[k].y *= inv; v[k].z *= inv; v[k].w *= inv;
        p4[k * 256 + tid] = v[k];
    }
}

// ---------------------------------------------------------------------------
extern "C" void kernel_launch(void* const* d_in, const int* in_sizes, int n_in,
                              void* d_out, int out_size) {
    const float* p = (const float*)d_in[0];
    const float* q = (const float*)d_in[1];
    if (in_sizes[0] > in_sizes[1]) { const float* t = p; p = q; q = t; }

    float* post = (float*)d_out;
    float* c    = post + (size_t)Q_ROWS * K_COLS;
    float* h    = c + Q_ROWS;

    cudaFuncSetAttribute(gemm_mma, cudaFuncAttributeMaxDynamicSharedMemorySize, SMEM_BYTES);

    int nwarps  = Q_ROWS + K_COLS;
    int nblocks = (nwarps * 32 + 255) / 256;
    prep_kernel<<<nblocks, 256>>>(q, p);

    dim3 grid(K_COLS / 128, Q_ROWS / 128);  // (8, 64)
    gemm_mma<<<grid, 256, SMEM_BYTES>>>(post);

    finalize_kernel<<<Q_ROWS / 8, 256>>>(post, c, h);
}

// round 11
// speedup vs baseline: 1.6080x; 1.6080x over previous
#include <cuda_runtime.h>
#include <cuda_fp16.h>
#include <math.h>
#include <stdint.h>

#define Q_ROWS 8192
#define K_COLS 1024
#define DDIM   1024
#define EPSV   1e-6f
#define NPART  32                 // 8 col-CTAs * 4 warp-cols

// -------- scratch (device globals; no allocation allowed) --------
__device__ float g_a[Q_ROWS];
__device__ float g_b[K_COLS];
__device__ float g_Sp[NPART][Q_ROWS];
__device__ float g_Tp[NPART][Q_ROWS];
__device__ float g_Mp[NPART][Q_ROWS];
__device__ __half g_qh[(size_t)Q_ROWS * DDIM];   // fp16 Q (16 MB)
__device__ __half g_ph[(size_t)K_COLS * DDIM];   // fp16 P (2 MB)

static __device__ __forceinline__ uint32_t smem_u32(const void* p) {
    uint32_t a;
    asm("{ .reg .u64 t; cvta.to.shared.u64 t, %1; cvt.u32.u64 %0, t; }" : "=r"(a) : "l"(p));
    return a;
}
static __device__ __forceinline__ void cp16(uint32_t sdst, const void* gsrc) {
    asm volatile("cp.async.cg.shared.global [%0], [%1], 16;" :: "r"(sdst), "l"(gsrc));
}
#define CP_COMMIT() asm volatile("cp.async.commit_group;" ::: "memory")
#define CP_WAIT1()  asm volatile("cp.async.wait_group 1;" ::: "memory")
#define CP_WAIT0()  asm volatile("cp.async.wait_group 0;" ::: "memory")

static __device__ __forceinline__ void ldsm4(uint32_t& r0, uint32_t& r1, uint32_t& r2,
                                             uint32_t& r3, uint32_t addr) {
    asm volatile("ldmatrix.sync.aligned.m8n8.x4.shared.b16 {%0,%1,%2,%3}, [%4];"
                 : "=r"(r0), "=r"(r1), "=r"(r2), "=r"(r3) : "r"(addr));
}
static __device__ __forceinline__ void mma_f16(float& c0, float& c1, float& c2, float& c3,
                                               uint32_t a0, uint32_t a1, uint32_t a2, uint32_t a3,
                                               uint32_t b0, uint32_t b1) {
    asm volatile(
        "mma.sync.aligned.m16n8k16.row.col.f32.f16.f16.f32 "
        "{%0,%1,%2,%3}, {%4,%5,%6,%7}, {%8,%9}, {%0,%1,%2,%3};"
        : "+f"(c0), "+f"(c1), "+f"(c2), "+f"(c3)
        : "r"(a0), "r"(a1), "r"(a2), "r"(a3), "r"(b0), "r"(b1));
}

// ---------------------------------------------------------------------------
// Prep: one warp per row. Computes a/b vectors, writes fp16 copies with
// fully vectorized 16B stores.
// ---------------------------------------------------------------------------
__global__ void prep_kernel(const float* __restrict__ q, const float* __restrict__ p) {
    int warp = (blockIdx.x * blockDim.x + threadIdx.x) >> 5;
    int lane = threadIdx.x & 31;
    if (warp >= Q_ROWS + K_COLS) return;

    const bool isQ = warp < Q_ROWS;
    const int  r   = isQ ? warp : warp - Q_ROWS;
    const float4* row4 = (const float4*)((isQ ? q : p) + (size_t)r * DDIM);
    uint4* out4 = (uint4*)((isQ ? g_qh : g_ph) + (size_t)r * DDIM);  // 8 halves per uint4

    float sq = 0.f, sm = 0.f;
    #pragma unroll
    for (int i = 0; i < (DDIM / 8) / 32; ++i) {   // 4 iterations, 8 floats each
        float4 v0 = row4[2 * (lane + i * 32)];
        float4 v1 = row4[2 * (lane + i * 32) + 1];
        sq += v0.x * v0.x + v0.y * v0.y + v0.z * v0.z + v0.w * v0.w;
        sq += v1.x * v1.x + v1.y * v1.y + v1.z * v1.z + v1.w * v1.w;
        sm += v0.x + v0.y + v0.z + v0.w + v1.x + v1.y + v1.z + v1.w;
        __half2 h0 = __floats2half2_rn(v0.x, v0.y);
        __half2 h1 = __floats2half2_rn(v0.z, v0.w);
        __half2 h2 = __floats2half2_rn(v1.x, v1.y);
        __half2 h3 = __floats2half2_rn(v1.z, v1.w);
        uint4 u;
        u.x = *(uint32_t*)&h0; u.y = *(uint32_t*)&h1;
        u.z = *(uint32_t*)&h2; u.w = *(uint32_t*)&h3;
        out4[lane + i * 32] = u;
    }
    #pragma unroll
    for (int o = 16; o > 0; o >>= 1) {
        sq += __shfl_down_sync(0xFFFFFFFFu, sq, o);
        sm += __shfl_down_sync(0xFFFFFFFFu, sm, o);
    }
    if (lane == 0) {
        if (isQ) g_a[r] = sq + 2.f * EPSV * sm;
        else     g_b[r] = sq - 2.f * EPSV * sm + (float)DDIM * EPSV * EPSV;
    }
}

// ---------------------------------------------------------------------------
// fp16 mma.sync m16n8k16 GEMM + fused epilogue, BK=64, 3-stage cp.async.
// CTA 128x128, 8 warps (2x4), warp tile 64x32, 16 mainloop iterations.
// SMEM rows padded to 72 halves. 2 CTAs/SM. NOTE: epilogue deliberately
// reloads g_a/g_b inline — hoisting them spills the accumulators (R9/R10).
// ---------------------------------------------------------------------------
#define BKH 64
#define LDH 72
#define ROW_BYTES (LDH * 2)                  // 144
#define A_BYTES   (128 * ROW_BYTES)          // 18432
#define STAGE_BYTES (2 * A_BYTES)            // 36864
#define NSTAGE 3
#define SMEM_BYTES (NSTAGE * STAGE_BYTES)    // 110592

__global__ void __launch_bounds__(256, 2) gemm_mma(float* __restrict__ post) {
    extern __shared__ char smc[];
    const uint32_t sb = smem_u32(smc);

    const int tid  = threadIdx.x;
    const int wid  = tid >> 5;
    const int lane = tid & 31;
    const int wm   = wid & 1;
    const int wn   = wid >> 1;
    const int g    = lane >> 2;
    const int cq   = lane & 3;
    const int bx = blockIdx.x, by = blockIdx.y;

    const __half* Qg = g_qh + (size_t)(by * 128) * DDIM;
    const __half* Pg = g_ph + (size_t)(bx * 128) * DDIM;

    auto issue = [&](int c, int s) {
        const int k0 = c * BKH;
        #pragma unroll
        for (int i = 0; i < 4; ++i) {
            int idx = tid + i * 256, row = idx >> 3, ch = idx & 7;
            uint32_t so = sb + s * STAGE_BYTES + row * ROW_BYTES + ch * 16;
            cp16(so, Qg + (size_t)row * DDIM + k0 + ch * 8);
            cp16(so + A_BYTES, Pg + (size_t)row * DDIM + k0 + ch * 8);
        }
        CP_COMMIT();
    };

    const uint32_t aOff = ((wm * 64 + (lane & 15)) * LDH + (lane >> 4) * 8) * 2;
    const uint32_t bOff = (uint32_t)A_BYTES +
        ((wn * 32 + (lane >> 4) * 8 + (lane & 7)) * LDH + ((lane >> 3) & 1) * 8) * 2;

    float C[4][4][4];
    #pragma unroll
    for (int i = 0; i < 4; ++i)
        #pragma unroll
        for (int j = 0; j < 4; ++j)
            #pragma unroll
            for (int r = 0; r < 4; ++r) C[i][j][r] = 0.f;

    issue(0, 0);
    issue(1, 1);

    for (int c = 0; c < 16; ++c) {
        const int s = c % NSTAGE;
        if (c < 15) CP_WAIT1(); else CP_WAIT0();
        __syncthreads();
        if (c + 2 < 16) issue(c + 2, (c + 2) % NSTAGE);

        const uint32_t aBase = sb + s * STAGE_BYTES + aOff;
        const uint32_t bBase = sb + s * STAGE_BYTES + bOff;
        #pragma unroll
        for (int ks = 0; ks < 4; ++ks) {
            const uint32_t kadd = ks * 32;
            uint32_t a[4][4], b[4][2];
            #pragma unroll
            for (int i = 0; i < 4; ++i)
                ldsm4(a[i][0], a[i][1], a[i][2], a[i][3],
                      aBase + i * (16 * ROW_BYTES) + kadd);
            #pragma unroll
            for (int jp = 0; jp < 2; ++jp)
                ldsm4(b[2 * jp][0], b[2 * jp][1], b[2 * jp + 1][0], b[2 * jp + 1][1],
                      bBase + jp * (16 * ROW_BYTES) + kadd);
            #pragma unroll
            for (int i = 0; i < 4; ++i)
                #pragma unroll
                for (int j = 0; j < 4; ++j)
                    mma_f16(C[i][j][0], C[i][j][1], C[i][j][2], C[i][j][3],
                            a[i][0], a[i][1], a[i][2], a[i][3], b[j][0], b[j][1]);
        }
    }

    // ---------------- fused epilogue on C registers ----------------
    #pragma unroll
    for (int i = 0; i < 4; ++i) {
        #pragma unroll
        for (int half = 0; half < 2; ++half) {
            const int row = by * 128 + wm * 64 + i * 16 + half * 8 + g;
            const float av = g_a[row];
            float S = 0.f, T = 0.f, M = 0.f;
            #pragma unroll
            for (int j = 0; j < 4; ++j) {
                const int col = bx * 128 + wn * 32 + j * 8 + 2 * cq;
                float cr0 = C[i][j][half * 2];
                float cr1 = C[i][j][half * 2 + 1];
                float d20 = av + g_b[col]     - 2.f * cr0;
                float d21 = av + g_b[col + 1] - 2.f * cr1;
                float di0 = sqrtf(fmaxf(d20, 0.f));
                float di1 = sqrtf(fmaxf(d21, 0.f));
                float e0 = __expf(-di0), e1 = __expf(-di1);
                S += e0 + e1;
                T += e0 * di0 + e1 * di1;
                M = fmaxf(M, fmaxf(e0, e1));
                *(float2*)(post + (size_t)row * K_COLS + col) = make_float2(e0, e1);
            }
            #pragma unroll
            for (int o = 1; o < 4; o <<= 1) {
                S += __shfl_xor_sync(0xFFFFFFFFu, S, o);
                T += __shfl_xor_sync(0xFFFFFFFFu, T, o);
                M = fmaxf(M, __shfl_xor_sync(0xFFFFFFFFu, M, o));
            }
            if (cq == 0) {
                const int part = bx * 4 + wn;
                g_Sp[part][row] = S;
                g_Tp[part][row] = T;
                g_Mp[part][row] = M;
            }
        }
    }
}

// ---------------------------------------------------------------------------
// Finalize: one block per row. The row load is issued FIRST so its DRAM
// latency overlaps warp 0's partial reduction.
// ---------------------------------------------------------------------------
__global__ void __launch_bounds__(256) finalize_kernel(float* __restrict__ post,
                                                       float* __restrict__ c_out,
                                                       float* __restrict__ h_out) {
    const int row = blockIdx.x;
    const int lane = threadIdx.x & 31;
    __shared__ float sInv;

    // issue row load early (overlaps the reduction below)
    float4* o = (float4*)(post + (size_t)row * K_COLS);
    float4 v = o[threadIdx.x];

    if (threadIdx.x < 32) {
        float S = g_Sp[lane][row];
        float T = g_Tp[lane][row];
        float M = g_Mp[lane][row];
        #pragma unroll
        for (int of = 16; of > 0; of >>= 1) {
            S += __shfl_xor_sync(0xFFFFFFFFu, S, of);
            T += __shfl_xor_sync(0xFFFFFFFFu, T, of);
            M = fmaxf(M, __shfl_xor_sync(0xFFFFFFFFu, M, of));
        }
        if (lane == 0) {
            c_out[row] = M / S;
            h_out[row] = logf(S) + T / S;
            sInv = 1.f / S;
        }
    }
    __syncthreads();
    const float inv = sInv;
    v.x *= inv; v.y *= inv; v.z *= inv; v.w *= inv;
    o[threadIdx.x] = v;
}

// ---------------------------------------------------------------------------
extern "C" void kernel_launch(void* const* d_in, const int* in_sizes, int n_in,
                              void* d_out, int out_size) {
    const float* p = (const float*)d_in[0];
    const float* q = (const float*)d_in[1];
    if (in_sizes[0] > in_sizes[1]) { const float* t = p; p = q; q = t; }

    float* post = (float*)d_out;
    float* c    = post + (size_t)Q_ROWS * K_COLS;
    float* h    = c + Q_ROWS;

    cudaFuncSetAttribute(gemm_mma, cudaFuncAttributeMaxDynamicSharedMemorySize, SMEM_BYTES);

    int nwarps  = Q_ROWS + K_COLS;
    int nblocks = (nwarps * 32 + 255) / 256;
    prep_kernel<<<nblocks, 256>>>(q, p);

    dim3 grid(K_COLS / 128, Q_ROWS / 128);  // (8, 64)
    gemm_mma<<<grid, 256, SMEM_BYTES>>>(post);

    finalize_kernel<<<Q_ROWS, 256>>>(post, c, h);
}

// round 12
// speedup vs baseline: 1.6635x; 1.0345x over previous
#include <cuda_runtime.h>
#include <cuda_fp16.h>
#include <math.h>
#include <stdint.h>

#define Q_ROWS 8192
#define K_COLS 1024
#define DDIM   1024
#define EPSV   1e-6f
#define NPART  32                 // 8 col-CTAs * 4 warp-cols

// -------- scratch (device globals; no allocation allowed) --------
__device__ float g_a[Q_ROWS];
__device__ float g_b[K_COLS];
__device__ float g_Sp[NPART][Q_ROWS];
__device__ float g_Tp[NPART][Q_ROWS];
__device__ float g_Mp[NPART][Q_ROWS];
__device__ __half g_qh[(size_t)Q_ROWS * DDIM];   // fp16 Q (16 MB)
__device__ __half g_ph[(size_t)K_COLS * DDIM];   // fp16 P (2 MB)

static __device__ __forceinline__ uint32_t smem_u32(const void* p) {
    uint32_t a;
    asm("{ .reg .u64 t; cvta.to.shared.u64 t, %1; cvt.u32.u64 %0, t; }" : "=r"(a) : "l"(p));
    return a;
}
static __device__ __forceinline__ void cp16(uint32_t sdst, const void* gsrc) {
    asm volatile("cp.async.cg.shared.global [%0], [%1], 16;" :: "r"(sdst), "l"(gsrc));
}
#define CP_COMMIT() asm volatile("cp.async.commit_group;" ::: "memory")
#define CP_WAIT1()  asm volatile("cp.async.wait_group 1;" ::: "memory")
#define CP_WAIT0()  asm volatile("cp.async.wait_group 0;" ::: "memory")

static __device__ __forceinline__ void ldsm4(uint32_t& r0, uint32_t& r1, uint32_t& r2,
                                             uint32_t& r3, uint32_t addr) {
    asm volatile("ldmatrix.sync.aligned.m8n8.x4.shared.b16 {%0,%1,%2,%3}, [%4];"
                 : "=r"(r0), "=r"(r1), "=r"(r2), "=r"(r3) : "r"(addr));
}
static __device__ __forceinline__ void mma_f16(float& c0, float& c1, float& c2, float& c3,
                                               uint32_t a0, uint32_t a1, uint32_t a2, uint32_t a3,
                                               uint32_t b0, uint32_t b1) {
    asm volatile(
        "mma.sync.aligned.m16n8k16.row.col.f32.f16.f16.f32 "
        "{%0,%1,%2,%3}, {%4,%5,%6,%7}, {%8,%9}, {%0,%1,%2,%3};"
        : "+f"(c0), "+f"(c1), "+f"(c2), "+f"(c3)
        : "r"(a0), "r"(a1), "r"(a2), "r"(a3), "r"(b0), "r"(b1));
}

// ---------------------------------------------------------------------------
// Prep: one warp per row. Computes a/b vectors, writes fp16 copies with
// fully vectorized 16B stores. (unchanged from R11 baseline)
// ---------------------------------------------------------------------------
__global__ void prep_kernel(const float* __restrict__ q, const float* __restrict__ p) {
    int warp = (blockIdx.x * blockDim.x + threadIdx.x) >> 5;
    int lane = threadIdx.x & 31;
    if (warp >= Q_ROWS + K_COLS) return;

    const bool isQ = warp < Q_ROWS;
    const int  r   = isQ ? warp : warp - Q_ROWS;
    const float4* row4 = (const float4*)((isQ ? q : p) + (size_t)r * DDIM);
    uint4* out4 = (uint4*)((isQ ? g_qh : g_ph) + (size_t)r * DDIM);

    float sq = 0.f, sm = 0.f;
    #pragma unroll
    for (int i = 0; i < (DDIM / 8) / 32; ++i) {
        float4 v0 = row4[2 * (lane + i * 32)];
        float4 v1 = row4[2 * (lane + i * 32) + 1];
        sq += v0.x * v0.x + v0.y * v0.y + v0.z * v0.z + v0.w * v0.w;
        sq += v1.x * v1.x + v1.y * v1.y + v1.z * v1.z + v1.w * v1.w;
        sm += v0.x + v0.y + v0.z + v0.w + v1.x + v1.y + v1.z + v1.w;
        __half2 h0 = __floats2half2_rn(v0.x, v0.y);
        __half2 h1 = __floats2half2_rn(v0.z, v0.w);
        __half2 h2 = __floats2half2_rn(v1.x, v1.y);
        __half2 h3 = __floats2half2_rn(v1.z, v1.w);
        uint4 u;
        u.x = *(uint32_t*)&h0; u.y = *(uint32_t*)&h1;
        u.z = *(uint32_t*)&h2; u.w = *(uint32_t*)&h3;
        out4[lane + i * 32] = u;
    }
    #pragma unroll
    for (int o = 16; o > 0; o >>= 1) {
        sq += __shfl_down_sync(0xFFFFFFFFu, sq, o);
        sm += __shfl_down_sync(0xFFFFFFFFu, sm, o);
    }
    if (lane == 0) {
        if (isQ) g_a[r] = sq + 2.f * EPSV * sm;
        else     g_b[r] = sq - 2.f * EPSV * sm + (float)DDIM * EPSV * EPSV;
    }
}

// ---------------------------------------------------------------------------
// fp16 mma.sync m16n8k16 GEMM + fused epilogue, BK=64, 3-stage cp.async.
// CTA 128x128, 8 warps (2x4), warp tile 64x32, 16 mainloop iterations.
// SMEM rows padded to 72 halves. 2 CTAs/SM. NOTE: epilogue deliberately
// reloads g_a/g_b inline — hoisting them spills the accumulators (R9/R10).
// (unchanged from R11 baseline)
// ---------------------------------------------------------------------------
#define BKH 64
#define LDH 72
#define ROW_BYTES (LDH * 2)                  // 144
#define A_BYTES   (128 * ROW_BYTES)          // 18432
#define STAGE_BYTES (2 * A_BYTES)            // 36864
#define NSTAGE 3
#define SMEM_BYTES (NSTAGE * STAGE_BYTES)    // 110592

__global__ void __launch_bounds__(256, 2) gemm_mma(float* __restrict__ post) {
    extern __shared__ char smc[];
    const uint32_t sb = smem_u32(smc);

    const int tid  = threadIdx.x;
    const int wid  = tid >> 5;
    const int lane = tid & 31;
    const int wm   = wid & 1;
    const int wn   = wid >> 1;
    const int g    = lane >> 2;
    const int cq   = lane & 3;
    const int bx = blockIdx.x, by = blockIdx.y;

    const __half* Qg = g_qh + (size_t)(by * 128) * DDIM;
    const __half* Pg = g_ph + (size_t)(bx * 128) * DDIM;

    auto issue = [&](int c, int s) {
        const int k0 = c * BKH;
        #pragma unroll
        for (int i = 0; i < 4; ++i) {
            int idx = tid + i * 256, row = idx >> 3, ch = idx & 7;
            uint32_t so = sb + s * STAGE_BYTES + row * ROW_BYTES + ch * 16;
            cp16(so, Qg + (size_t)row * DDIM + k0 + ch * 8);
            cp16(so + A_BYTES, Pg + (size_t)row * DDIM + k0 + ch * 8);
        }
        CP_COMMIT();
    };

    const uint32_t aOff = ((wm * 64 + (lane & 15)) * LDH + (lane >> 4) * 8) * 2;
    const uint32_t bOff = (uint32_t)A_BYTES +
        ((wn * 32 + (lane >> 4) * 8 + (lane & 7)) * LDH + ((lane >> 3) & 1) * 8) * 2;

    float C[4][4][4];
    #pragma unroll
    for (int i = 0; i < 4; ++i)
        #pragma unroll
        for (int j = 0; j < 4; ++j)
            #pragma unroll
            for (int r = 0; r < 4; ++r) C[i][j][r] = 0.f;

    issue(0, 0);
    issue(1, 1);

    for (int c = 0; c < 16; ++c) {
        const int s = c % NSTAGE;
        if (c < 15) CP_WAIT1(); else CP_WAIT0();
        __syncthreads();
        if (c + 2 < 16) issue(c + 2, (c + 2) % NSTAGE);

        const uint32_t aBase = sb + s * STAGE_BYTES + aOff;
        const uint32_t bBase = sb + s * STAGE_BYTES + bOff;
        #pragma unroll
        for (int ks = 0; ks < 4; ++ks) {
            const uint32_t kadd = ks * 32;
            uint32_t a[4][4], b[4][2];
            #pragma unroll
            for (int i = 0; i < 4; ++i)
                ldsm4(a[i][0], a[i][1], a[i][2], a[i][3],
                      aBase + i * (16 * ROW_BYTES) + kadd);
            #pragma unroll
            for (int jp = 0; jp < 2; ++jp)
                ldsm4(b[2 * jp][0], b[2 * jp][1], b[2 * jp + 1][0], b[2 * jp + 1][1],
                      bBase + jp * (16 * ROW_BYTES) + kadd);
            #pragma unroll
            for (int i = 0; i < 4; ++i)
                #pragma unroll
                for (int j = 0; j < 4; ++j)
                    mma_f16(C[i][j][0], C[i][j][1], C[i][j][2], C[i][j][3],
                            a[i][0], a[i][1], a[i][2], a[i][3], b[j][0], b[j][1]);
        }
    }

    // ---------------- fused epilogue on C registers ----------------
    #pragma unroll
    for (int i = 0; i < 4; ++i) {
        #pragma unroll
        for (int half = 0; half < 2; ++half) {
            const int row = by * 128 + wm * 64 + i * 16 + half * 8 + g;
            const float av = g_a[row];
            float S = 0.f, T = 0.f, M = 0.f;
            #pragma unroll
            for (int j = 0; j < 4; ++j) {
                const int col = bx * 128 + wn * 32 + j * 8 + 2 * cq;
                float cr0 = C[i][j][half * 2];
                float cr1 = C[i][j][half * 2 + 1];
                float d20 = av + g_b[col]     - 2.f * cr0;
                float d21 = av + g_b[col + 1] - 2.f * cr1;
                float di0 = sqrtf(fmaxf(d20, 0.f));
                float di1 = sqrtf(fmaxf(d21, 0.f));
                float e0 = __expf(-di0), e1 = __expf(-di1);
                S += e0 + e1;
                T += e0 * di0 + e1 * di1;
                M = fmaxf(M, fmaxf(e0, e1));
                *(float2*)(post + (size_t)row * K_COLS + col) = make_float2(e0, e1);
            }
            #pragma unroll
            for (int o = 1; o < 4; o <<= 1) {
                S += __shfl_xor_sync(0xFFFFFFFFu, S, o);
                T += __shfl_xor_sync(0xFFFFFFFFu, T, o);
                M = fmaxf(M, __shfl_xor_sync(0xFFFFFFFFu, M, o));
            }
            if (cq == 0) {
                const int part = bx * 4 + wn;
                g_Sp[part][row] = S;
                g_Tp[part][row] = T;
                g_Mp[part][row] = M;
            }
        }
    }
}

// ---------------------------------------------------------------------------
// Finalize (ONLY change this round): 8 rows per block (1024 blocks).
// Each thread issues 8 independent LDG.128 up front (MLP=8); warp w reduces
// row (row0+w)'s 32 partials while those loads are in flight.
// ---------------------------------------------------------------------------
__global__ void __launch_bounds__(256) finalize_kernel(float* __restrict__ post,
                                                       float* __restrict__ c_out,
                                                       float* __restrict__ h_out) {
    const int tid  = threadIdx.x;
    const int wid  = tid >> 5;
    const int lane = tid & 31;
    const int row0 = blockIdx.x * 8;
    __shared__ float sInv[8];

    // issue all 8 row-chunks early (independent loads, MLP=8)
    float4* p4 = (float4*)(post + (size_t)row0 * K_COLS);
    float4 v[8];
    #pragma unroll
    for (int k = 0; k < 8; ++k) v[k] = p4[k * 256 + tid];

    // warp w reduces row row0+w (overlaps the loads above)
    {
        const int row = row0 + wid;
        float S = g_Sp[lane][row];
        float T = g_Tp[lane][row];
        float M = g_Mp[lane][row];
        #pragma unroll
        for (int of = 16; of > 0; of >>= 1) {
            S += __shfl_xor_sync(0xFFFFFFFFu, S, of);
            T += __shfl_xor_sync(0xFFFFFFFFu, T, of);
            M = fmaxf(M, __shfl_xor_sync(0xFFFFFFFFu, M, of));
        }
        if (lane == 0) {
            c_out[row] = M / S;
            h_out[row] = logf(S) + T / S;
            sInv[wid] = 1.f / S;
        }
    }
    __syncthreads();

    #pragma unroll
    for (int k = 0; k < 8; ++k) {
        const float inv = sInv[k];
        v[k].x *= inv; v[k].y *= inv; v[k].z *= inv; v[k].w *= inv;
        p4[k * 256 + tid] = v[k];
    }
}

// ---------------------------------------------------------------------------
extern "C" void kernel_launch(void* const* d_in, const int* in_sizes, int n_in,
                              void* d_out, int out_size) {
    const float* p = (const float*)d_in[0];
    const float* q = (const float*)d_in[1];
    if (in_sizes[0] > in_sizes[1]) { const float* t = p; p = q; q = t; }

    float* post = (float*)d_out;
    float* c    = post + (size_t)Q_ROWS * K_COLS;
    float* h    = c + Q_ROWS;

    cudaFuncSetAttribute(gemm_mma, cudaFuncAttributeMaxDynamicSharedMemorySize, SMEM_BYTES);

    int nwarps  = Q_ROWS + K_COLS;
    int nblocks = (nwarps * 32 + 255) / 256;
    prep_kernel<<<nblocks, 256>>>(q, p);

    dim3 grid(K_COLS / 128, Q_ROWS / 128);  // (8, 64)
    gemm_mma<<<grid, 256, SMEM_BYTES>>>(post);

    finalize_kernel<<<Q_ROWS / 8, 256>>>(post, c, h);
}

// round 13
// speedup vs baseline: 1.6753x; 1.0071x over previous
#include <cuda_runtime.h>
#include <cuda_fp16.h>
#include <math.h>
#include <stdint.h>

#define Q_ROWS 8192
#define K_COLS 1024
#define DDIM   1024
#define EPSV   1e-6f
#define NPART  32                 // 8 col-CTAs * 4 warp-cols

// -------- scratch (device globals; no allocation allowed) --------
__device__ float g_a[Q_ROWS];
__device__ float g_b[K_COLS];
__device__ float g_Sp[NPART][Q_ROWS];
__device__ float g_Tp[NPART][Q_ROWS];
__device__ float g_Mp[NPART][Q_ROWS];
__device__ __half g_qh[(size_t)Q_ROWS * DDIM];   // fp16 Q (16 MB)
__device__ __half g_ph[(size_t)K_COLS * DDIM];   // fp16 P (2 MB)

static __device__ __forceinline__ uint32_t smem_u32(const void* p) {
    uint32_t a;
    asm("{ .reg .u64 t; cvta.to.shared.u64 t, %1; cvt.u32.u64 %0, t; }" : "=r"(a) : "l"(p));
    return a;
}
static __device__ __forceinline__ void cp16(uint32_t sdst, const void* gsrc) {
    asm volatile("cp.async.cg.shared.global [%0], [%1], 16;" :: "r"(sdst), "l"(gsrc));
}
#define CP_COMMIT() asm volatile("cp.async.commit_group;" ::: "memory")
#define CP_WAIT1()  asm volatile("cp.async.wait_group 1;" ::: "memory")
#define CP_WAIT0()  asm volatile("cp.async.wait_group 0;" ::: "memory")

static __device__ __forceinline__ void ldsm4(uint32_t& r0, uint32_t& r1, uint32_t& r2,
                                             uint32_t& r3, uint32_t addr) {
    asm volatile("ldmatrix.sync.aligned.m8n8.x4.shared.b16 {%0,%1,%2,%3}, [%4];"
                 : "=r"(r0), "=r"(r1), "=r"(r2), "=r"(r3) : "r"(addr));
}
static __device__ __forceinline__ void mma_f16(float& c0, float& c1, float& c2, float& c3,
                                               uint32_t a0, uint32_t a1, uint32_t a2, uint32_t a3,
                                               uint32_t b0, uint32_t b1) {
    asm volatile(
        "mma.sync.aligned.m16n8k16.row.col.f32.f16.f16.f32 "
        "{%0,%1,%2,%3}, {%4,%5,%6,%7}, {%8,%9}, {%0,%1,%2,%3};"
        : "+f"(c0), "+f"(c1), "+f"(c2), "+f"(c3)
        : "r"(a0), "r"(a1), "r"(a2), "r"(a3), "r"(b0), "r"(b1));
}

// ---------------------------------------------------------------------------
// Prep (ONLY change this round): TWO rows per warp -> 16 independent LDG.128
// in flight per thread-slot and two interleaved reduction chains.
// Rows 2w and 2w+1 never straddle the Q/P boundary (8192 is even).
// ---------------------------------------------------------------------------
__global__ void prep_kernel(const float* __restrict__ q, const float* __restrict__ p) {
    int warp = (blockIdx.x * blockDim.x + threadIdx.x) >> 5;
    int lane = threadIdx.x & 31;
    if (warp >= (Q_ROWS + K_COLS) / 2) return;

    const int r0 = 2 * warp;
    const bool isQ = r0 < Q_ROWS;
    const int  rr  = isQ ? r0 : r0 - Q_ROWS;
    const float* base = isQ ? q : p;
    const float4* rowA = (const float4*)(base + (size_t)rr * DDIM);
    const float4* rowB = (const float4*)(base + (size_t)(rr + 1) * DDIM);
    __half* outb = (isQ ? g_qh : g_ph);
    uint4* outA = (uint4*)(outb + (size_t)rr * DDIM);
    uint4* outB = (uint4*)(outb + (size_t)(rr + 1) * DDIM);

    float sqA = 0.f, smA = 0.f, sqB = 0.f, smB = 0.f;
    #pragma unroll
    for (int i = 0; i < (DDIM / 8) / 32; ++i) {   // 4 iterations, 8 floats per row
        float4 a0 = rowA[2 * (lane + i * 32)];
        float4 a1 = rowA[2 * (lane + i * 32) + 1];
        float4 b0 = rowB[2 * (lane + i * 32)];
        float4 b1 = rowB[2 * (lane + i * 32) + 1];

        sqA += a0.x * a0.x + a0.y * a0.y + a0.z * a0.z + a0.w * a0.w
             + a1.x * a1.x + a1.y * a1.y + a1.z * a1.z + a1.w * a1.w;
        smA += a0.x + a0.y + a0.z + a0.w + a1.x + a1.y + a1.z + a1.w;
        sqB += b0.x * b0.x + b0.y * b0.y + b0.z * b0.z + b0.w * b0.w
             + b1.x * b1.x + b1.y * b1.y + b1.z * b1.z + b1.w * b1.w;
        smB += b0.x + b0.y + b0.z + b0.w + b1.x + b1.y + b1.z + b1.w;

        __half2 ha0 = __floats2half2_rn(a0.x, a0.y);
        __half2 ha1 = __floats2half2_rn(a0.z, a0.w);
        __half2 ha2 = __floats2half2_rn(a1.x, a1.y);
        __half2 ha3 = __floats2half2_rn(a1.z, a1.w);
        uint4 ua;
        ua.x = *(uint32_t*)&ha0; ua.y = *(uint32_t*)&ha1;
        ua.z = *(uint32_t*)&ha2; ua.w = *(uint32_t*)&ha3;
        outA[lane + i * 32] = ua;

        __half2 hb0 = __floats2half2_rn(b0.x, b0.y);
        __half2 hb1 = __floats2half2_rn(b0.z, b0.w);
        __half2 hb2 = __floats2half2_rn(b1.x, b1.y);
        __half2 hb3 = __floats2half2_rn(b1.z, b1.w);
        uint4 ub;
        ub.x = *(uint32_t*)&hb0; ub.y = *(uint32_t*)&hb1;
        ub.z = *(uint32_t*)&hb2; ub.w = *(uint32_t*)&hb3;
        outB[lane + i * 32] = ub;
    }
    #pragma unroll
    for (int o = 16; o > 0; o >>= 1) {
        sqA += __shfl_down_sync(0xFFFFFFFFu, sqA, o);
        smA += __shfl_down_sync(0xFFFFFFFFu, smA, o);
        sqB += __shfl_down_sync(0xFFFFFFFFu, sqB, o);
        smB += __shfl_down_sync(0xFFFFFFFFu, smB, o);
    }
    if (lane == 0) {
        if (isQ) {
            g_a[rr]     = sqA + 2.f * EPSV * smA;
            g_a[rr + 1] = sqB + 2.f * EPSV * smB;
        } else {
            g_b[rr]     = sqA - 2.f * EPSV * smA + (float)DDIM * EPSV * EPSV;
            g_b[rr + 1] = sqB - 2.f * EPSV * smB + (float)DDIM * EPSV * EPSV;
        }
    }
}

// ---------------------------------------------------------------------------
// fp16 mma.sync m16n8k16 GEMM + fused epilogue, BK=64, 3-stage cp.async.
// CTA 128x128, 8 warps (2x4), warp tile 64x32, 16 mainloop iterations.
// SMEM rows padded to 72 halves. 2 CTAs/SM. NOTE: epilogue deliberately
// reloads g_a/g_b inline — hoisting them spills the accumulators (R9/R10).
// (unchanged from R12 best)
// ---------------------------------------------------------------------------
#define BKH 64
#define LDH 72
#define ROW_BYTES (LDH * 2)                  // 144
#define A_BYTES   (128 * ROW_BYTES)          // 18432
#define STAGE_BYTES (2 * A_BYTES)            // 36864
#define NSTAGE 3
#define SMEM_BYTES (NSTAGE * STAGE_BYTES)    // 110592

__global__ void __launch_bounds__(256, 2) gemm_mma(float* __restrict__ post) {
    extern __shared__ char smc[];
    const uint32_t sb = smem_u32(smc);

    const int tid  = threadIdx.x;
    const int wid  = tid >> 5;
    const int lane = tid & 31;
    const int wm   = wid & 1;
    const int wn   = wid >> 1;
    const int g    = lane >> 2;
    const int cq   = lane & 3;
    const int bx = blockIdx.x, by = blockIdx.y;

    const __half* Qg = g_qh + (size_t)(by * 128) * DDIM;
    const __half* Pg = g_ph + (size_t)(bx * 128) * DDIM;

    auto issue = [&](int c, int s) {
        const int k0 = c * BKH;
        #pragma unroll
        for (int i = 0; i < 4; ++i) {
            int idx = tid + i * 256, row = idx >> 3, ch = idx & 7;
            uint32_t so = sb + s * STAGE_BYTES + row * ROW_BYTES + ch * 16;
            cp16(so, Qg + (size_t)row * DDIM + k0 + ch * 8);
            cp16(so + A_BYTES, Pg + (size_t)row * DDIM + k0 + ch * 8);
        }
        CP_COMMIT();
    };

    const uint32_t aOff = ((wm * 64 + (lane & 15)) * LDH + (lane >> 4) * 8) * 2;
    const uint32_t bOff = (uint32_t)A_BYTES +
        ((wn * 32 + (lane >> 4) * 8 + (lane & 7)) * LDH + ((lane >> 3) & 1) * 8) * 2;

    float C[4][4][4];
    #pragma unroll
    for (int i = 0; i < 4; ++i)
        #pragma unroll
        for (int j = 0; j < 4; ++j)
            #pragma unroll
            for (int r = 0; r < 4; ++r) C[i][j][r] = 0.f;

    issue(0, 0);
    issue(1, 1);

    for (int c = 0; c < 16; ++c) {
        const int s = c % NSTAGE;
        if (c < 15) CP_WAIT1(); else CP_WAIT0();
        __syncthreads();
        if (c + 2 < 16) issue(c + 2, (c + 2) % NSTAGE);

        const uint32_t aBase = sb + s * STAGE_BYTES + aOff;
        const uint32_t bBase = sb + s * STAGE_BYTES + bOff;
        #pragma unroll
        for (int ks = 0; ks < 4; ++ks) {
            const uint32_t kadd = ks * 32;
            uint32_t a[4][4], b[4][2];
            #pragma unroll
            for (int i = 0; i < 4; ++i)
                ldsm4(a[i][0], a[i][1], a[i][2], a[i][3],
                      aBase + i * (16 * ROW_BYTES) + kadd);
            #pragma unroll
            for (int jp = 0; jp < 2; ++jp)
                ldsm4(b[2 * jp][0], b[2 * jp][1], b[2 * jp + 1][0], b[2 * jp + 1][1],
                      bBase + jp * (16 * ROW_BYTES) + kadd);
            #pragma unroll
            for (int i = 0; i < 4; ++i)
                #pragma unroll
                for (int j = 0; j < 4; ++j)
                    mma_f16(C[i][j][0], C[i][j][1], C[i][j][2], C[i][j][3],
                            a[i][0], a[i][1], a[i][2], a[i][3], b[j][0], b[j][1]);
        }
    }

    // ---------------- fused epilogue on C registers ----------------
    #pragma unroll
    for (int i = 0; i < 4; ++i) {
        #pragma unroll
        for (int half = 0; half < 2; ++half) {
            const int row = by * 128 + wm * 64 + i * 16 + half * 8 + g;
            const float av = g_a[row];
            float S = 0.f, T = 0.f, M = 0.f;
            #pragma unroll
            for (int j = 0; j < 4; ++j) {
                const int col = bx * 128 + wn * 32 + j * 8 + 2 * cq;
                float cr0 = C[i][j][half * 2];
                float cr1 = C[i][j][half * 2 + 1];
                float d20 = av + g_b[col]     - 2.f * cr0;
                float d21 = av + g_b[col + 1] - 2.f * cr1;
                float di0 = sqrtf(fmaxf(d20, 0.f));
                float di1 = sqrtf(fmaxf(d21, 0.f));
                float e0 = __expf(-di0), e1 = __expf(-di1);
                S += e0 + e1;
                T += e0 * di0 + e1 * di1;
                M = fmaxf(M, fmaxf(e0, e1));
                *(float2*)(post + (size_t)row * K_COLS + col) = make_float2(e0, e1);
            }
            #pragma unroll
            for (int o = 1; o < 4; o <<= 1) {
                S += __shfl_xor_sync(0xFFFFFFFFu, S, o);
                T += __shfl_xor_sync(0xFFFFFFFFu, T, o);
                M = fmaxf(M, __shfl_xor_sync(0xFFFFFFFFu, M, o));
            }
            if (cq == 0) {
                const int part = bx * 4 + wn;
                g_Sp[part][row] = S;
                g_Tp[part][row] = T;
                g_Mp[part][row] = M;
            }
        }
    }
}

// ---------------------------------------------------------------------------
// Finalize: 8 rows per block (1024 blocks), MLP=8. (unchanged from R12 best)
// ---------------------------------------------------------------------------
__global__ void __launch_bounds__(256) finalize_kernel(float* __restrict__ post,
                                                       float* __restrict__ c_out,
                                                       float* __restrict__ h_out) {
    const int tid  = threadIdx.x;
    const int wid  = tid >> 5;
    const int lane = tid & 31;
    const int row0 = blockIdx.x * 8;
    __shared__ float sInv[8];

    float4* p4 = (float4*)(post + (size_t)row0 * K_COLS);
    float4 v[8];
    #pragma unroll
    for (int k = 0; k < 8; ++k) v[k] = p4[k * 256 + tid];

    {
        const int row = row0 + wid;
        float S = g_Sp[lane][row];
        float T = g_Tp[lane][row];
        float M = g_Mp[lane][row];
        #pragma unroll
        for (int of = 16; of > 0; of >>= 1) {
            S += __shfl_xor_sync(0xFFFFFFFFu, S, of);
            T += __shfl_xor_sync(0xFFFFFFFFu, T, of);
            M = fmaxf(M, __shfl_xor_sync(0xFFFFFFFFu, M, of));
        }
        if (lane == 0) {
            c_out[row] = M / S;
            h_out[row] = logf(S) + T / S;
            sInv[wid] = 1.f / S;
        }
    }
    __syncthreads();

    #pragma unroll
    for (int k = 0; k < 8; ++k) {
        const float inv = sInv[k];
        v[k].x *= inv; v[k].y *= inv; v[k].z *= inv; v[k].w *= inv;
        p4[k * 256 + tid] = v[k];
    }
}

// ---------------------------------------------------------------------------
extern "C" void kernel_launch(void* const* d_in, const int* in_sizes, int n_in,
                              void* d_out, int out_size) {
    const float* p = (const float*)d_in[0];
    const float* q = (const float*)d_in[1];
    if (in_sizes[0] > in_sizes[1]) { const float* t = p; p = q; q = t; }

    float* post = (float*)d_out;
    float* c    = post + (size_t)Q_ROWS * K_COLS;
    float* h    = c + Q_ROWS;

    cudaFuncSetAttribute(gemm_mma, cudaFuncAttributeMaxDynamicSharedMemorySize, SMEM_BYTES);

    int nwarps  = (Q_ROWS + K_COLS) / 2;         // 4608 warps (2 rows each)
    int nblocks = (nwarps * 32 + 255) / 256;     // 576 blocks
    prep_kernel<<<nblocks, 256>>>(q, p);

    dim3 grid(K_COLS / 128, Q_ROWS / 128);  // (8, 64)
    gemm_mma<<<grid, 256, SMEM_BYTES>>>(post);

    finalize_kernel<<<Q_ROWS / 8, 256>>>(post, c, h);
}

// round 14
// speedup vs baseline: 1.7356x; 1.0360x over previous
#include <cuda_runtime.h>
#include <cuda_fp16.h>
#include <math.h>
#include <stdint.h>

#define Q_ROWS 8192
#define K_COLS 1024
#define DDIM   1024
#define EPSV   1e-6f
#define NPART  32                 // 8 col-CTAs * 4 warp-cols

// -------- scratch (device globals; no allocation allowed) --------
__device__ float g_a[Q_ROWS];
__device__ float g_b[K_COLS];
__device__ float g_Sp[NPART][Q_ROWS];
__device__ float g_Tp[NPART][Q_ROWS];
__device__ float g_Mp[NPART][Q_ROWS];
__device__ __half g_qh[(size_t)Q_ROWS * DDIM];   // fp16 Q (16 MB)
__device__ __half g_ph[(size_t)K_COLS * DDIM];   // fp16 P (2 MB)

static __device__ __forceinline__ uint32_t smem_u32(const void* p) {
    uint32_t a;
    asm("{ .reg .u64 t; cvta.to.shared.u64 t, %1; cvt.u32.u64 %0, t; }" : "=r"(a) : "l"(p));
    return a;
}
static __device__ __forceinline__ float sqrt_fast(float x) {
    float r;
    asm("sqrt.approx.f32 %0, %1;" : "=f"(r) : "f"(x));
    return r;
}
static __device__ __forceinline__ void cp16(uint32_t sdst, const void* gsrc) {
    asm volatile("cp.async.cg.shared.global [%0], [%1], 16;" :: "r"(sdst), "l"(gsrc));
}
#define CP_COMMIT() asm volatile("cp.async.commit_group;" ::: "memory")
#define CP_WAIT1()  asm volatile("cp.async.wait_group 1;" ::: "memory")
#define CP_WAIT0()  asm volatile("cp.async.wait_group 0;" ::: "memory")

static __device__ __forceinline__ void ldsm4(uint32_t& r0, uint32_t& r1, uint32_t& r2,
                                             uint32_t& r3, uint32_t addr) {
    asm volatile("ldmatrix.sync.aligned.m8n8.x4.shared.b16 {%0,%1,%2,%3}, [%4];"
                 : "=r"(r0), "=r"(r1), "=r"(r2), "=r"(r3) : "r"(addr));
}
static __device__ __forceinline__ void mma_f16(float& c0, float& c1, float& c2, float& c3,
                                               uint32_t a0, uint32_t a1, uint32_t a2, uint32_t a3,
                                               uint32_t b0, uint32_t b1) {
    asm volatile(
        "mma.sync.aligned.m16n8k16.row.col.f32.f16.f16.f32 "
        "{%0,%1,%2,%3}, {%4,%5,%6,%7}, {%8,%9}, {%0,%1,%2,%3};"
        : "+f"(c0), "+f"(c1), "+f"(c2), "+f"(c3)
        : "r"(a0), "r"(a1), "r"(a2), "r"(a3), "r"(b0), "r"(b1));
}

// ---------------------------------------------------------------------------
// Prep: TWO rows per warp (16 independent LDG.128 in flight, two interleaved
// reduction chains). Unchanged from R13 best.
// ---------------------------------------------------------------------------
__global__ void prep_kernel(const float* __restrict__ q, const float* __restrict__ p) {
    int warp = (blockIdx.x * blockDim.x + threadIdx.x) >> 5;
    int lane = threadIdx.x & 31;
    if (warp >= (Q_ROWS + K_COLS) / 2) return;

    const int r0 = 2 * warp;
    const bool isQ = r0 < Q_ROWS;
    const int  rr  = isQ ? r0 : r0 - Q_ROWS;
    const float* base = isQ ? q : p;
    const float4* rowA = (const float4*)(base + (size_t)rr * DDIM);
    const float4* rowB = (const float4*)(base + (size_t)(rr + 1) * DDIM);
    __half* outb = (isQ ? g_qh : g_ph);
    uint4* outA = (uint4*)(outb + (size_t)rr * DDIM);
    uint4* outB = (uint4*)(outb + (size_t)(rr + 1) * DDIM);

    float sqA = 0.f, smA = 0.f, sqB = 0.f, smB = 0.f;
    #pragma unroll
    for (int i = 0; i < (DDIM / 8) / 32; ++i) {
        float4 a0 = rowA[2 * (lane + i * 32)];
        float4 a1 = rowA[2 * (lane + i * 32) + 1];
        float4 b0 = rowB[2 * (lane + i * 32)];
        float4 b1 = rowB[2 * (lane + i * 32) + 1];

        sqA += a0.x * a0.x + a0.y * a0.y + a0.z * a0.z + a0.w * a0.w
             + a1.x * a1.x + a1.y * a1.y + a1.z * a1.z + a1.w * a1.w;
        smA += a0.x + a0.y + a0.z + a0.w + a1.x + a1.y + a1.z + a1.w;
        sqB += b0.x * b0.x + b0.y * b0.y + b0.z * b0.z + b0.w * b0.w
             + b1.x * b1.x + b1.y * b1.y + b1.z * b1.z + b1.w * b1.w;
        smB += b0.x + b0.y + b0.z + b0.w + b1.x + b1.y + b1.z + b1.w;

        __half2 ha0 = __floats2half2_rn(a0.x, a0.y);
        __half2 ha1 = __floats2half2_rn(a0.z, a0.w);
        __half2 ha2 = __floats2half2_rn(a1.x, a1.y);
        __half2 ha3 = __floats2half2_rn(a1.z, a1.w);
        uint4 ua;
        ua.x = *(uint32_t*)&ha0; ua.y = *(uint32_t*)&ha1;
        ua.z = *(uint32_t*)&ha2; ua.w = *(uint32_t*)&ha3;
        outA[lane + i * 32] = ua;

        __half2 hb0 = __floats2half2_rn(b0.x, b0.y);
        __half2 hb1 = __floats2half2_rn(b0.z, b0.w);
        __half2 hb2 = __floats2half2_rn(b1.x, b1.y);
        __half2 hb3 = __floats2half2_rn(b1.z, b1.w);
        uint4 ub;
        ub.x = *(uint32_t*)&hb0; ub.y = *(uint32_t*)&hb1;
        ub.z = *(uint32_t*)&hb2; ub.w = *(uint32_t*)&hb3;
        outB[lane + i * 32] = ub;
    }
    #pragma unroll
    for (int o = 16; o > 0; o >>= 1) {
        sqA += __shfl_down_sync(0xFFFFFFFFu, sqA, o);
        smA += __shfl_down_sync(0xFFFFFFFFu, smA, o);
        sqB += __shfl_down_sync(0xFFFFFFFFu, sqB, o);
        smB += __shfl_down_sync(0xFFFFFFFFu, smB, o);
    }
    if (lane == 0) {
        if (isQ) {
            g_a[rr]     = sqA + 2.f * EPSV * smA;
            g_a[rr + 1] = sqB + 2.f * EPSV * smB;
        } else {
            g_b[rr]     = sqA - 2.f * EPSV * smA + (float)DDIM * EPSV * EPSV;
            g_b[rr + 1] = sqB - 2.f * EPSV * smB + (float)DDIM * EPSV * EPSV;
        }
    }
}

// ---------------------------------------------------------------------------
// fp16 mma.sync m16n8k16 GEMM + fused epilogue, BK=64, 3-stage cp.async.
// CTA 128x128, 8 warps (2x4), warp tile 64x32, 16 mainloop iterations.
// ONLY change this round: sqrtf -> sqrt.approx.f32 in the epilogue.
// NOTE: epilogue deliberately reloads g_a/g_b inline — hoisting spills (R9/R10).
// ---------------------------------------------------------------------------
#define BKH 64
#define LDH 72
#define ROW_BYTES (LDH * 2)                  // 144
#define A_BYTES   (128 * ROW_BYTES)          // 18432
#define STAGE_BYTES (2 * A_BYTES)            // 36864
#define NSTAGE 3
#define SMEM_BYTES (NSTAGE * STAGE_BYTES)    // 110592

__global__ void __launch_bounds__(256, 2) gemm_mma(float* __restrict__ post) {
    extern __shared__ char smc[];
    const uint32_t sb = smem_u32(smc);

    const int tid  = threadIdx.x;
    const int wid  = tid >> 5;
    const int lane = tid & 31;
    const int wm   = wid & 1;
    const int wn   = wid >> 1;
    const int g    = lane >> 2;
    const int cq   = lane & 3;
    const int bx = blockIdx.x, by = blockIdx.y;

    const __half* Qg = g_qh + (size_t)(by * 128) * DDIM;
    const __half* Pg = g_ph + (size_t)(bx * 128) * DDIM;

    auto issue = [&](int c, int s) {
        const int k0 = c * BKH;
        #pragma unroll
        for (int i = 0; i < 4; ++i) {
            int idx = tid + i * 256, row = idx >> 3, ch = idx & 7;
            uint32_t so = sb + s * STAGE_BYTES + row * ROW_BYTES + ch * 16;
            cp16(so, Qg + (size_t)row * DDIM + k0 + ch * 8);
            cp16(so + A_BYTES, Pg + (size_t)row * DDIM + k0 + ch * 8);
        }
        CP_COMMIT();
    };

    const uint32_t aOff = ((wm * 64 + (lane & 15)) * LDH + (lane >> 4) * 8) * 2;
    const uint32_t bOff = (uint32_t)A_BYTES +
        ((wn * 32 + (lane >> 4) * 8 + (lane & 7)) * LDH + ((lane >> 3) & 1) * 8) * 2;

    float C[4][4][4];
    #pragma unroll
    for (int i = 0; i < 4; ++i)
        #pragma unroll
        for (int j = 0; j < 4; ++j)
            #pragma unroll
            for (int r = 0; r < 4; ++r) C[i][j][r] = 0.f;

    issue(0, 0);
    issue(1, 1);

    for (int c = 0; c < 16; ++c) {
        const int s = c % NSTAGE;
        if (c < 15) CP_WAIT1(); else CP_WAIT0();
        __syncthreads();
        if (c + 2 < 16) issue(c + 2, (c + 2) % NSTAGE);

        const uint32_t aBase = sb + s * STAGE_BYTES + aOff;
        const uint32_t bBase = sb + s * STAGE_BYTES + bOff;
        #pragma unroll
        for (int ks = 0; ks < 4; ++ks) {
            const uint32_t kadd = ks * 32;
            uint32_t a[4][4], b[4][2];
            #pragma unroll
            for (int i = 0; i < 4; ++i)
                ldsm4(a[i][0], a[i][1], a[i][2], a[i][3],
                      aBase + i * (16 * ROW_BYTES) + kadd);
            #pragma unroll
            for (int jp = 0; jp < 2; ++jp)
                ldsm4(b[2 * jp][0], b[2 * jp][1], b[2 * jp + 1][0], b[2 * jp + 1][1],
                      bBase + jp * (16 * ROW_BYTES) + kadd);
            #pragma unroll
            for (int i = 0; i < 4; ++i)
                #pragma unroll
                for (int j = 0; j < 4; ++j)
                    mma_f16(C[i][j][0], C[i][j][1], C[i][j][2], C[i][j][3],
                            a[i][0], a[i][1], a[i][2], a[i][3], b[j][0], b[j][1]);
        }
    }

    // ---------------- fused epilogue on C registers ----------------
    #pragma unroll
    for (int i = 0; i < 4; ++i) {
        #pragma unroll
        for (int half = 0; half < 2; ++half) {
            const int row = by * 128 + wm * 64 + i * 16 + half * 8 + g;
            const float av = g_a[row];
            float S = 0.f, T = 0.f, M = 0.f;
            #pragma unroll
            for (int j = 0; j < 4; ++j) {
                const int col = bx * 128 + wn * 32 + j * 8 + 2 * cq;
                float cr0 = C[i][j][half * 2];
                float cr1 = C[i][j][half * 2 + 1];
                float d20 = av + g_b[col]     - 2.f * cr0;
                float d21 = av + g_b[col + 1] - 2.f * cr1;
                float di0 = sqrt_fast(fmaxf(d20, 0.f));
                float di1 = sqrt_fast(fmaxf(d21, 0.f));
                float e0 = __expf(-di0), e1 = __expf(-di1);
                S += e0 + e1;
                T += e0 * di0 + e1 * di1;
                M = fmaxf(M, fmaxf(e0, e1));
                *(float2*)(post + (size_t)row * K_COLS + col) = make_float2(e0, e1);
            }
            #pragma unroll
            for (int o = 1; o < 4; o <<= 1) {
                S += __shfl_xor_sync(0xFFFFFFFFu, S, o);
                T += __shfl_xor_sync(0xFFFFFFFFu, T, o);
                M = fmaxf(M, __shfl_xor_sync(0xFFFFFFFFu, M, o));
            }
            if (cq == 0) {
                const int part = bx * 4 + wn;
                g_Sp[part][row] = S;
                g_Tp[part][row] = T;
                g_Mp[part][row] = M;
            }
        }
    }
}

// ---------------------------------------------------------------------------
// Finalize: 8 rows per block (1024 blocks), MLP=8. Unchanged from R12 best.
// ---------------------------------------------------------------------------
__global__ void __launch_bounds__(256) finalize_kernel(float* __restrict__ post,
                                                       float* __restrict__ c_out,
                                                       float* __restrict__ h_out) {
    const int tid  = threadIdx.x;
    const int wid  = tid >> 5;
    const int lane = tid & 31;
    const int row0 = blockIdx.x * 8;
    __shared__ float sInv[8];

    float4* p4 = (float4*)(post + (size_t)row0 * K_COLS);
    float4 v[8];
    #pragma unroll
    for (int k = 0; k < 8; ++k) v[k] = p4[k * 256 + tid];

    {
        const int row = row0 + wid;
        float S = g_Sp[lane][row];
        float T = g_Tp[lane][row];
        float M = g_Mp[lane][row];
        #pragma unroll
        for (int of = 16; of > 0; of >>= 1) {
            S += __shfl_xor_sync(0xFFFFFFFFu, S, of);
            T += __shfl_xor_sync(0xFFFFFFFFu, T, of);
            M = fmaxf(M, __shfl_xor_sync(0xFFFFFFFFu, M, of));
        }
        if (lane == 0) {
            c_out[row] = M / S;
            h_out[row] = logf(S) + T / S;
            sInv[wid] = 1.f / S;
        }
    }
    __syncthreads();

    #pragma unroll
    for (int k = 0; k < 8; ++k) {
        const float inv = sInv[k];
        v[k].x *= inv; v[k].y *= inv; v[k].z *= inv; v[k].w *= inv;
        p4[k * 256 + tid] = v[k];
    }
}

// ---------------------------------------------------------------------------
extern "C" void kernel_launch(void* const* d_in, const int* in_sizes, int n_in,
                              void* d_out, int out_size) {
    const float* p = (const float*)d_in[0];
    const float* q = (const float*)d_in[1];
    if (in_sizes[0] > in_sizes[1]) { const float* t = p; p = q; q = t; }

    float* post = (float*)d_out;
    float* c    = post + (size_t)Q_ROWS * K_COLS;
    float* h    = c + Q_ROWS;

    cudaFuncSetAttribute(gemm_mma, cudaFuncAttributeMaxDynamicSharedMemorySize, SMEM_BYTES);

    int nwarps  = (Q_ROWS + K_COLS) / 2;         // 4608 warps (2 rows each)
    int nblocks = (nwarps * 32 + 255) / 256;     // 576 blocks
    prep_kernel<<<nblocks, 256>>>(q, p);

    dim3 grid(K_COLS / 128, Q_ROWS / 128);  // (8, 64)
    gemm_mma<<<grid, 256, SMEM_BYTES>>>(post);

    finalize_kernel<<<Q_ROWS / 8, 256>>>(post, c, h);
}

// round 15
// speedup vs baseline: 1.7403x; 1.0027x over previous
#include <cuda_runtime.h>
#include <cuda_fp16.h>
#include <math.h>
#include <stdint.h>

#define Q_ROWS 8192
#define K_COLS 1024
#define DDIM   1024
#define EPSV   1e-6f
#define NPART  32                 // 8 col-CTAs * 4 warp-cols

// -------- scratch (device globals; no allocation allowed) --------
__device__ float g_a[Q_ROWS];
__device__ float g_b[K_COLS];
__device__ float g_Sp[NPART][Q_ROWS];
__device__ float g_Tp[NPART][Q_ROWS];
__device__ float g_Mp[NPART][Q_ROWS];
__device__ __half g_qh[(size_t)Q_ROWS * DDIM];   // fp16 Q (16 MB)
__device__ __half g_ph[(size_t)K_COLS * DDIM];   // fp16 P (2 MB)

static __device__ __forceinline__ uint32_t smem_u32(const void* p) {
    uint32_t a;
    asm("{ .reg .u64 t; cvta.to.shared.u64 t, %1; cvt.u32.u64 %0, t; }" : "=r"(a) : "l"(p));
    return a;
}
static __device__ __forceinline__ float sqrt_fast(float x) {
    float r;
    asm("sqrt.approx.f32 %0, %1;" : "=f"(r) : "f"(x));
    return r;
}
static __device__ __forceinline__ void cp16(uint32_t sdst, const void* gsrc) {
    asm volatile("cp.async.cg.shared.global [%0], [%1], 16;" :: "r"(sdst), "l"(gsrc));
}
#define CP_COMMIT() asm volatile("cp.async.commit_group;" ::: "memory")
#define CP_WAIT1()  asm volatile("cp.async.wait_group 1;" ::: "memory")
#define CP_WAIT0()  asm volatile("cp.async.wait_group 0;" ::: "memory")

static __device__ __forceinline__ void ldsm4(uint32_t& r0, uint32_t& r1, uint32_t& r2,
                                             uint32_t& r3, uint32_t addr) {
    asm volatile("ldmatrix.sync.aligned.m8n8.x4.shared.b16 {%0,%1,%2,%3}, [%4];"
                 : "=r"(r0), "=r"(r1), "=r"(r2), "=r"(r3) : "r"(addr));
}
static __device__ __forceinline__ void mma_f16(float& c0, float& c1, float& c2, float& c3,
                                               uint32_t a0, uint32_t a1, uint32_t a2, uint32_t a3,
                                               uint32_t b0, uint32_t b1) {
    asm volatile(
        "mma.sync.aligned.m16n8k16.row.col.f32.f16.f16.f32 "
        "{%0,%1,%2,%3}, {%4,%5,%6,%7}, {%8,%9}, {%0,%1,%2,%3};"
        : "+f"(c0), "+f"(c1), "+f"(c2), "+f"(c3)
        : "r"(a0), "r"(a1), "r"(a2), "r"(a3), "r"(b0), "r"(b1));
}

// ---------------------------------------------------------------------------
// Prep (ONLY change this round): TWO rows per warp + explicit software
// pipeline — iteration i+1's 4 loads are issued before iteration i's
// convert/accumulate work, keeping 8 LDG.128 in flight per thread.
// ---------------------------------------------------------------------------
__global__ void prep_kernel(const float* __restrict__ q, const float* __restrict__ p) {
    int warp = (blockIdx.x * blockDim.x + threadIdx.x) >> 5;
    int lane = threadIdx.x & 31;
    if (warp >= (Q_ROWS + K_COLS) / 2) return;

    const int r0 = 2 * warp;
    const bool isQ = r0 < Q_ROWS;
    const int  rr  = isQ ? r0 : r0 - Q_ROWS;
    const float* base = isQ ? q : p;
    const float4* rowA = (const float4*)(base + (size_t)rr * DDIM);
    const float4* rowB = (const float4*)(base + (size_t)(rr + 1) * DDIM);
    __half* outb = (isQ ? g_qh : g_ph);
    uint4* outA = (uint4*)(outb + (size_t)rr * DDIM);
    uint4* outB = (uint4*)(outb + (size_t)(rr + 1) * DDIM);

    float sqA = 0.f, smA = 0.f, sqB = 0.f, smB = 0.f;

    // pipeline registers: current group (a0,a1,b0,b1), next group (na0,...)
    float4 a0 = rowA[2 * lane];
    float4 a1 = rowA[2 * lane + 1];
    float4 b0 = rowB[2 * lane];
    float4 b1 = rowB[2 * lane + 1];

    #pragma unroll
    for (int i = 0; i < 4; ++i) {
        float4 na0, na1, nb0, nb1;
        if (i < 3) {   // prefetch next group while current converts
            na0 = rowA[2 * (lane + (i + 1) * 32)];
            na1 = rowA[2 * (lane + (i + 1) * 32) + 1];
            nb0 = rowB[2 * (lane + (i + 1) * 32)];
            nb1 = rowB[2 * (lane + (i + 1) * 32) + 1];
        }

        sqA += a0.x * a0.x + a0.y * a0.y + a0.z * a0.z + a0.w * a0.w
             + a1.x * a1.x + a1.y * a1.y + a1.z * a1.z + a1.w * a1.w;
        smA += a0.x + a0.y + a0.z + a0.w + a1.x + a1.y + a1.z + a1.w;
        sqB += b0.x * b0.x + b0.y * b0.y + b0.z * b0.z + b0.w * b0.w
             + b1.x * b1.x + b1.y * b1.y + b1.z * b1.z + b1.w * b1.w;
        smB += b0.x + b0.y + b0.z + b0.w + b1.x + b1.y + b1.z + b1.w;

        __half2 ha0 = __floats2half2_rn(a0.x, a0.y);
        __half2 ha1 = __floats2half2_rn(a0.z, a0.w);
        __half2 ha2 = __floats2half2_rn(a1.x, a1.y);
        __half2 ha3 = __floats2half2_rn(a1.z, a1.w);
        uint4 ua;
        ua.x = *(uint32_t*)&ha0; ua.y = *(uint32_t*)&ha1;
        ua.z = *(uint32_t*)&ha2; ua.w = *(uint32_t*)&ha3;
        outA[lane + i * 32] = ua;

        __half2 hb0 = __floats2half2_rn(b0.x, b0.y);
        __half2 hb1 = __floats2half2_rn(b0.z, b0.w);
        __half2 hb2 = __floats2half2_rn(b1.x, b1.y);
        __half2 hb3 = __floats2half2_rn(b1.z, b1.w);
        uint4 ub;
        ub.x = *(uint32_t*)&hb0; ub.y = *(uint32_t*)&hb1;
        ub.z = *(uint32_t*)&hb2; ub.w = *(uint32_t*)&hb3;
        outB[lane + i * 32] = ub;

        if (i < 3) { a0 = na0; a1 = na1; b0 = nb0; b1 = nb1; }
    }

    #pragma unroll
    for (int o = 16; o > 0; o >>= 1) {
        sqA += __shfl_down_sync(0xFFFFFFFFu, sqA, o);
        smA += __shfl_down_sync(0xFFFFFFFFu, smA, o);
        sqB += __shfl_down_sync(0xFFFFFFFFu, sqB, o);
        smB += __shfl_down_sync(0xFFFFFFFFu, smB, o);
    }
    if (lane == 0) {
        if (isQ) {
            g_a[rr]     = sqA + 2.f * EPSV * smA;
            g_a[rr + 1] = sqB + 2.f * EPSV * smB;
        } else {
            g_b[rr]     = sqA - 2.f * EPSV * smA + (float)DDIM * EPSV * EPSV;
            g_b[rr + 1] = sqB - 2.f * EPSV * smB + (float)DDIM * EPSV * EPSV;
        }
    }
}

// ---------------------------------------------------------------------------
// fp16 mma.sync m16n8k16 GEMM + fused epilogue, BK=64, 3-stage cp.async.
// CTA 128x128, 8 warps (2x4), warp tile 64x32, 16 mainloop iterations.
// Unchanged from R14 best (sqrt.approx epilogue; no g_a/g_b hoist).
// ---------------------------------------------------------------------------
#define BKH 64
#define LDH 72
#define ROW_BYTES (LDH * 2)                  // 144
#define A_BYTES   (128 * ROW_BYTES)          // 18432
#define STAGE_BYTES (2 * A_BYTES)            // 36864
#define NSTAGE 3
#define SMEM_BYTES (NSTAGE * STAGE_BYTES)    // 110592

__global__ void __launch_bounds__(256, 2) gemm_mma(float* __restrict__ post) {
    extern __shared__ char smc[];
    const uint32_t sb = smem_u32(smc);

    const int tid  = threadIdx.x;
    const int wid  = tid >> 5;
    const int lane = tid & 31;
    const int wm   = wid & 1;
    const int wn   = wid >> 1;
    const int g    = lane >> 2;
    const int cq   = lane & 3;
    const int bx = blockIdx.x, by = blockIdx.y;

    const __half* Qg = g_qh + (size_t)(by * 128) * DDIM;
    const __half* Pg = g_ph + (size_t)(bx * 128) * DDIM;

    auto issue = [&](int c, int s) {
        const int k0 = c * BKH;
        #pragma unroll
        for (int i = 0; i < 4; ++i) {
            int idx = tid + i * 256, row = idx >> 3, ch = idx & 7;
            uint32_t so = sb + s * STAGE_BYTES + row * ROW_BYTES + ch * 16;
            cp16(so, Qg + (size_t)row * DDIM + k0 + ch * 8);
            cp16(so + A_BYTES, Pg + (size_t)row * DDIM + k0 + ch * 8);
        }
        CP_COMMIT();
    };

    const uint32_t aOff = ((wm * 64 + (lane & 15)) * LDH + (lane >> 4) * 8) * 2;
    const uint32_t bOff = (uint32_t)A_BYTES +
        ((wn * 32 + (lane >> 4) * 8 + (lane & 7)) * LDH + ((lane >> 3) & 1) * 8) * 2;

    float C[4][4][4];
    #pragma unroll
    for (int i = 0; i < 4; ++i)
        #pragma unroll
        for (int j = 0; j < 4; ++j)
            #pragma unroll
            for (int r = 0; r < 4; ++r) C[i][j][r] = 0.f;

    issue(0, 0);
    issue(1, 1);

    for (int c = 0; c < 16; ++c) {
        const int s = c % NSTAGE;
        if (c < 15) CP_WAIT1(); else CP_WAIT0();
        __syncthreads();
        if (c + 2 < 16) issue(c + 2, (c + 2) % NSTAGE);

        const uint32_t aBase = sb + s * STAGE_BYTES + aOff;
        const uint32_t bBase = sb + s * STAGE_BYTES + bOff;
        #pragma unroll
        for (int ks = 0; ks < 4; ++ks) {
            const uint32_t kadd = ks * 32;
            uint32_t a[4][4], b[4][2];
            #pragma unroll
            for (int i = 0; i < 4; ++i)
                ldsm4(a[i][0], a[i][1], a[i][2], a[i][3],
                      aBase + i * (16 * ROW_BYTES) + kadd);
            #pragma unroll
            for (int jp = 0; jp < 2; ++jp)
                ldsm4(b[2 * jp][0], b[2 * jp][1], b[2 * jp + 1][0], b[2 * jp + 1][1],
                      bBase + jp * (16 * ROW_BYTES) + kadd);
            #pragma unroll
            for (int i = 0; i < 4; ++i)
                #pragma unroll
                for (int j = 0; j < 4; ++j)
                    mma_f16(C[i][j][0], C[i][j][1], C[i][j][2], C[i][j][3],
                            a[i][0], a[i][1], a[i][2], a[i][3], b[j][0], b[j][1]);
        }
    }

    // ---------------- fused epilogue on C registers ----------------
    #pragma unroll
    for (int i = 0; i < 4; ++i) {
        #pragma unroll
        for (int half = 0; half < 2; ++half) {
            const int row = by * 128 + wm * 64 + i * 16 + half * 8 + g;
            const float av = g_a[row];
            float S = 0.f, T = 0.f, M = 0.f;
            #pragma unroll
            for (int j = 0; j < 4; ++j) {
                const int col = bx * 128 + wn * 32 + j * 8 + 2 * cq;
                float cr0 = C[i][j][half * 2];
                float cr1 = C[i][j][half * 2 + 1];
                float d20 = av + g_b[col]     - 2.f * cr0;
                float d21 = av + g_b[col + 1] - 2.f * cr1;
                float di0 = sqrt_fast(fmaxf(d20, 0.f));
                float di1 = sqrt_fast(fmaxf(d21, 0.f));
                float e0 = __expf(-di0), e1 = __expf(-di1);
                S += e0 + e1;
                T += e0 * di0 + e1 * di1;
                M = fmaxf(M, fmaxf(e0, e1));
                *(float2*)(post + (size_t)row * K_COLS + col) = make_float2(e0, e1);
            }
            #pragma unroll
            for (int o = 1; o < 4; o <<= 1) {
                S += __shfl_xor_sync(0xFFFFFFFFu, S, o);
                T += __shfl_xor_sync(0xFFFFFFFFu, T, o);
                M = fmaxf(M, __shfl_xor_sync(0xFFFFFFFFu, M, o));
            }
            if (cq == 0) {
                const int part = bx * 4 + wn;
                g_Sp[part][row] = S;
                g_Tp[part][row] = T;
                g_Mp[part][row] = M;
            }
        }
    }
}

// ---------------------------------------------------------------------------
// Finalize: 8 rows per block (1024 blocks), MLP=8. Unchanged from R12 best.
// ---------------------------------------------------------------------------
__global__ void __launch_bounds__(256) finalize_kernel(float* __restrict__ post,
                                                       float* __restrict__ c_out,
                                                       float* __restrict__ h_out) {
    const int tid  = threadIdx.x;
    const int wid  = tid >> 5;
    const int lane = tid & 31;
    const int row0 = blockIdx.x * 8;
    __shared__ float sInv[8];

    float4* p4 = (float4*)(post + (size_t)row0 * K_COLS);
    float4 v[8];
    #pragma unroll
    for (int k = 0; k < 8; ++k) v[k] = p4[k * 256 + tid];

    {
        const int row = row0 + wid;
        float S = g_Sp[lane][row];
        float T = g_Tp[lane][row];
        float M = g_Mp[lane][row];
        #pragma unroll
        for (int of = 16; of > 0; of >>= 1) {
            S += __shfl_xor_sync(0xFFFFFFFFu, S, of);
            T += __shfl_xor_sync(0xFFFFFFFFu, T, of);
            M = fmaxf(M, __shfl_xor_sync(0xFFFFFFFFu, M, of));
        }
        if (lane == 0) {
            c_out[row] = M / S;
            h_out[row] = logf(S) + T / S;
            sInv[wid] = 1.f / S;
        }
    }
    __syncthreads();

    #pragma unroll
    for (int k = 0; k < 8; ++k) {
        const float inv = sInv[k];
        v[k].x *= inv; v[k].y *= inv; v[k].z *= inv; v[k].w *= inv;
        p4[k * 256 + tid] = v[k];
    }
}

// ---------------------------------------------------------------------------
extern "C" void kernel_launch(void* const* d_in, const int* in_sizes, int n_in,
                              void* d_out, int out_size) {
    const float* p = (const float*)d_in[0];
    const float* q = (const float*)d_in[1];
    if (in_sizes[0] > in_sizes[1]) { const float* t = p; p = q; q = t; }

    float* post = (float*)d_out;
    float* c    = post + (size_t)Q_ROWS * K_COLS;
    float* h    = c + Q_ROWS;

    cudaFuncSetAttribute(gemm_mma, cudaFuncAttributeMaxDynamicSharedMemorySize, SMEM_BYTES);

    int nwarps  = (Q_ROWS + K_COLS) / 2;         // 4608 warps (2 rows each)
    int nblocks = (nwarps * 32 + 255) / 256;     // 576 blocks
    prep_kernel<<<nblocks, 256>>>(q, p);

    dim3 grid(K_COLS / 128, Q_ROWS / 128);  // (8, 64)
    gemm_mma<<<grid, 256, SMEM_BYTES>>>(post);

    finalize_kernel<<<Q_ROWS / 8, 256>>>(post, c, h);
}